// round 13
// baseline (speedup 1.0000x reference)
#include <cuda_runtime.h>
#include <math.h>
#include <stdint.h>

// B=128, T=256, W=256, D=128, C=256, K=12, Tp=244, TEMP=0.1
#define N_BT     32768
#define TP       244
#define NROWS_L  374784
// gemm smem: 2 buf x 4 arrays x 128x36 words + 128 bias
#define GEMM_SMEM ((2*4*4608 + 128)*4)
// fused logits smem: U stage 18432 + Z dbl-buf 36864 words
#define FUS_SMEM (55296*4)
// GRU6 smem
#define GRU6_SMEM (2*2048*4)

// ---------------- packed f32x2 helpers -----------------------------------
#define FMA2(d,a,b) asm("fma.rn.f32x2 %0, %1, %2, %0;" : "+l"(d) : "l"(a), "l"(b))
__device__ __forceinline__ void unpack2(unsigned long long v, float& lo, float& hi) {
    asm("mov.b64 {%0, %1}, %2;" : "=f"(lo), "=f"(hi) : "l"(v));
}
__device__ __forceinline__ float pairsum(unsigned long long v) {
    float a, b; unpack2(v, a, b); return a + b;
}
__device__ __forceinline__ uint32_t s2u(const void* p) {
    uint32_t a; asm("{ .reg .u64 t; cvta.to.shared.u64 t, %1; cvt.u32.u64 %0, t; }" : "=r"(a) : "l"(p));
    return a;
}
__device__ __forceinline__ uint32_t mapa_u32(uint32_t addr, uint32_t rank) {
    uint32_t r; asm("mapa.shared::cluster.u32 %0, %1, %2;" : "=r"(r) : "r"(addr), "r"(rank));
    return r;
}
__device__ __forceinline__ void st_cluster_f32(uint32_t addr, float v) {
    asm volatile("st.shared::cluster.f32 [%0], %1;" :: "r"(addr), "f"(v) : "memory");
}
__device__ __forceinline__ float fsig(float x)  { return 1.f / (1.f + __expf(-x)); }
__device__ __forceinline__ float ftanh(float x) { return 1.f - 2.f / (1.f + __expf(2.f*x)); }

// ---------------- tf32 mma helpers ---------------------------------------
__device__ __forceinline__ uint32_t f2tf(float x) {
    uint32_t r; asm("cvt.rna.tf32.f32 %0, %1;" : "=r"(r) : "f"(x)); return r;
}
__device__ __forceinline__ void cvt_hl(float4 x, uint4& h, uint4& l) {
    h.x = f2tf(x.x); l.x = f2tf(x.x - __uint_as_float(h.x));
    h.y = f2tf(x.y); l.y = f2tf(x.y - __uint_as_float(h.y));
    h.z = f2tf(x.z); l.z = f2tf(x.z - __uint_as_float(h.z));
    h.w = f2tf(x.w); l.w = f2tf(x.w - __uint_as_float(h.w));
}
__device__ __forceinline__ void mma8(float* c, const uint32_t* a, const uint32_t* b) {
    asm volatile("mma.sync.aligned.m16n8k8.row.col.f32.tf32.tf32.f32 "
        "{%0,%1,%2,%3}, {%4,%5,%6,%7}, {%8,%9}, {%0,%1,%2,%3};"
        : "+f"(c[0]), "+f"(c[1]), "+f"(c[2]), "+f"(c[3])
        : "r"(a[0]), "r"(a[1]), "r"(a[2]), "r"(a[3]), "r"(b[0]), "r"(b[1]));
}

// ---------------- scratch ------------------------------------------------
__device__ __align__(16) float g_z   [4194304];   // [32768,128] normalized z
__device__ __align__(16) float g_c   [8388608];   // [32768,256] c_seq
__device__ __align__(16) float g_h1  [8388608];   // [32768,256]
__device__ __align__(16) float g_gx  [25165824];  // [32768,768]
__device__ __align__(16) float g_w1T [65536];
__device__ __align__(16) float g_w2T [32768];
__device__ __align__(16) float g_WkT [393216];    // [12][128][256]
__device__ __align__(16) float g_part[12288];

// ---------------- prep: transposes ---------------------------------------
__global__ void prep_a(const float* __restrict__ w1, const float* __restrict__ w2)
{
    long i = (long)blockIdx.x * 256 + threadIdx.x;
    if (i < 65536) {
        int n = (int)(i >> 8), k = (int)(i & 255);
        g_w1T[n*256 + k] = w1[k*256 + n];
    }
    if (i < 32768) {
        int n = (int)(i >> 8), k = (int)(i & 255);
        g_w2T[n*256 + k] = w2[k*128 + n];
    }
}
__global__ void prep_b(const float* __restrict__ wk)
{
    long i = (long)blockIdx.x * 256 + threadIdx.x;
    if (i < 393216) {
        long kk = i / 32768; long r = i % 32768;
        int d = (int)(r >> 8), c = (int)(r & 255);
        g_WkT[kk*32768 + d*256 + c] = wk[kk*32768 + c*128 + d];
    }
}

// ---------------- 3xTF32 mma.sync NT-GEMM (hi/lo staged in smem) ---------
__global__ __launch_bounds__(256, 1) void mma_gemm(
    const float* __restrict__ A, const float* __restrict__ Bm,
    const float* __restrict__ bias, float* __restrict__ Cm,
    int M, int N, int K, int relu, int mode,
    long sB, long sBias, long sC)
{
    extern __shared__ uint32_t smu[];
    float* sbias = (float*)(smu + 36864);
    float* rs    = (float*)smu;          // overlay [128][17]
    float* rinv  = (float*)(smu + 2176);

    const float* Bz = Bm  + (long)blockIdx.z * sB;
    const float* bz = bias + (long)blockIdx.z * sBias;
    float*       Cz = Cm  + (long)blockIdx.z * sC;
    int m0 = blockIdx.y * 128, n0 = blockIdx.x * 128;

    int tid = threadIdx.x;
    int wid = tid >> 5, lane = tid & 31;
    int wm = wid >> 2, wn = wid & 3;
    int gid = lane >> 2, tig = lane & 3;

    if (tid < 128) sbias[tid] = bz[n0 + tid];

    const float* Ag = A  + (long)m0 * K;
    const float* Bg = Bz + (long)n0 * K;

    float c[4][4][4];
    #pragma unroll
    for (int i = 0; i < 4; i++)
        #pragma unroll
        for (int j = 0; j < 4; j++)
            #pragma unroll
            for (int q = 0; q < 4; q++) c[i][j][q] = 0.f;

    float4 ra[4], rb[4];
    #pragma unroll
    for (int l = 0; l < 4; l++) {
        int u = tid + l*256, r = u >> 3, c4 = u & 7;
        ra[l] = *(const float4*)(Ag + (long)r*K + c4*4);
        rb[l] = *(const float4*)(Bg + (long)r*K + c4*4);
    }
    #pragma unroll
    for (int l = 0; l < 4; l++) {
        int u = tid + l*256, r = u >> 3, c4 = u & 7;
        uint4 h, lo;
        cvt_hl(ra[l], h, lo);
        *(uint4*)(smu + 0    + r*36 + c4*4) = h;
        *(uint4*)(smu + 4608 + r*36 + c4*4) = lo;
        cvt_hl(rb[l], h, lo);
        *(uint4*)(smu + 9216  + r*36 + c4*4) = h;
        *(uint4*)(smu + 13824 + r*36 + c4*4) = lo;
    }
    __syncthreads();

    int NC = K >> 5;
    for (int kc = 0; kc < NC; kc++) {
        const uint32_t* base = smu + (kc & 1)*18432;
        bool nxt = (kc + 1 < NC);
        if (nxt) {
            int k0 = (kc + 1) * 32;
            #pragma unroll
            for (int l = 0; l < 4; l++) {
                int u = tid + l*256, r = u >> 3, c4 = u & 7;
                ra[l] = *(const float4*)(Ag + (long)r*K + k0 + c4*4);
                rb[l] = *(const float4*)(Bg + (long)r*K + k0 + c4*4);
            }
        }
        #pragma unroll
        for (int ks = 0; ks < 4; ks++) {
            int k = ks * 8;
            uint32_t ah[4][4], al[4][4];
            #pragma unroll
            for (int i = 0; i < 4; i++) {
                int r0 = wm*64 + i*16 + gid;
                ah[i][0] = base[r0*36 + k + tig];
                ah[i][1] = base[(r0+8)*36 + k + tig];
                ah[i][2] = base[r0*36 + k + tig + 4];
                ah[i][3] = base[(r0+8)*36 + k + tig + 4];
                al[i][0] = base[4608 + r0*36 + k + tig];
                al[i][1] = base[4608 + (r0+8)*36 + k + tig];
                al[i][2] = base[4608 + r0*36 + k + tig + 4];
                al[i][3] = base[4608 + (r0+8)*36 + k + tig + 4];
            }
            #pragma unroll
            for (int j = 0; j < 4; j++) {
                int n = wn*32 + j*8 + gid;
                uint32_t bh[2], bl[2];
                bh[0] = base[9216 + n*36 + k + tig];
                bh[1] = base[9216 + n*36 + k + tig + 4];
                bl[0] = base[13824 + n*36 + k + tig];
                bl[1] = base[13824 + n*36 + k + tig + 4];
                #pragma unroll
                for (int i = 0; i < 4; i++) {
                    mma8(c[i][j], ah[i], bh);
                    mma8(c[i][j], ah[i], bl);
                    mma8(c[i][j], al[i], bh);
                }
            }
        }
        if (nxt) {
            uint32_t* nb = smu + ((kc + 1) & 1)*18432;
            #pragma unroll
            for (int l = 0; l < 4; l++) {
                int u = tid + l*256, r = u >> 3, c4 = u & 7;
                uint4 h, lo;
                cvt_hl(ra[l], h, lo);
                *(uint4*)(nb + 0    + r*36 + c4*4) = h;
                *(uint4*)(nb + 4608 + r*36 + c4*4) = lo;
                cvt_hl(rb[l], h, lo);
                *(uint4*)(nb + 9216  + r*36 + c4*4) = h;
                *(uint4*)(nb + 13824 + r*36 + c4*4) = lo;
            }
            __syncthreads();
        }
    }

    #pragma unroll
    for (int i = 0; i < 4; i++)
        #pragma unroll
        for (int j = 0; j < 4; j++) {
            int colb = wn*32 + j*8 + tig*2;
            c[i][j][0] += sbias[colb]; c[i][j][1] += sbias[colb+1];
            c[i][j][2] += sbias[colb]; c[i][j][3] += sbias[colb+1];
        }

    if (mode == 0) {
        #pragma unroll
        for (int i = 0; i < 4; i++) {
            int r0 = m0 + wm*64 + i*16 + gid;
            #pragma unroll
            for (int j = 0; j < 4; j++) {
                int colb = n0 + wn*32 + j*8 + tig*2;
                float2 v0 = make_float2(c[i][j][0], c[i][j][1]);
                float2 v1 = make_float2(c[i][j][2], c[i][j][3]);
                if (relu) {
                    v0.x = fmaxf(v0.x, 0.f); v0.y = fmaxf(v0.y, 0.f);
                    v1.x = fmaxf(v1.x, 0.f); v1.y = fmaxf(v1.y, 0.f);
                }
                *(float2*)(Cz + (long)r0*N + colb)     = v0;
                *(float2*)(Cz + (long)(r0+8)*N + colb) = v1;
            }
        }
    } else {
        __syncthreads();
        #pragma unroll
        for (int i = 0; i < 4; i++) {
            float ss0 = 0.f, ss1 = 0.f;
            #pragma unroll
            for (int j = 0; j < 4; j++) {
                ss0 += c[i][j][0]*c[i][j][0] + c[i][j][1]*c[i][j][1];
                ss1 += c[i][j][2]*c[i][j][2] + c[i][j][3]*c[i][j][3];
            }
            int r0 = wm*64 + i*16 + gid;
            rs[r0*17 + wn*4 + tig]     = ss0;
            rs[(r0+8)*17 + wn*4 + tig] = ss1;
        }
        __syncthreads();
        if (tid < 128) {
            float ss = 0.f;
            #pragma unroll
            for (int x = 0; x < 16; x++) ss += rs[tid*17 + x];
            float inv = 1.f / fmaxf(sqrtf(ss), 1e-12f);
            if (mode == 1) inv *= 10.f;
            rinv[tid] = inv;
        }
        __syncthreads();
        #pragma unroll
        for (int i = 0; i < 4; i++) {
            int rr = wm*64 + i*16 + gid;
            float sc0 = rinv[rr], sc1 = rinv[rr+8];
            int r0 = m0 + rr;
            #pragma unroll
            for (int j = 0; j < 4; j++) {
                int colb = n0 + wn*32 + j*8 + tig*2;
                *(float2*)(Cz + (long)r0*N + colb) =
                    make_float2(c[i][j][0]*sc0, c[i][j][1]*sc0);
                *(float2*)(Cz + (long)(r0+8)*N + colb) =
                    make_float2(c[i][j][2]*sc1, c[i][j][3]*sc1);
            }
        }
    }
}

// ---------------- FUSED: U-tile GEMM + row-norm + logits + reductions ----
// grid (4 t-tiles, 128 b, 12 k); block 256 (8 warps: wm in {0,1}, wn in {0..3}).
// Phase 1: U[64][128] = c[t0..t0+63] @ WkT[k]^T + Wkb[k], rows *= 10/||row||.
//          U hi/lo staged persistently in smem (all 4 d-chunks).
// Phase 2: logits = U @ Z^T, fused logsumexp/pos/negmax.
// smem (words): Uh@0 (9216), Ul@9216 (9216), work area @18432 (36864):
//   phase1 staging: Ah@18432, Al@+2304, Bh@+4608, Bl@+9216 (within work area)
//   phase1 rs/rinv overlay @18432 after MMAs; phase2 Z buf b @ 18432+b*18432
//   phase2 red arrays overlay @18432 after Z consumed.
__global__ __launch_bounds__(256, 1) void fused_logits(
    const float* __restrict__ Wkb)
{
    extern __shared__ uint32_t smu[];
    int tile = blockIdx.x, b = blockIdx.y, kk = blockIdx.z;
    int t0 = tile * 64;
    int tid = threadIdx.x;
    int wid = tid >> 5, lane = tid & 31;
    int wm = wid >> 2, wn = wid & 3;
    int gid = lane >> 2, tig = lane & 3;

    // ================= phase 1: U tile =================
    const float* Cg = g_c + ((long)b*256 + t0) * 256;      // [64][256]
    const float* Wg = g_WkT + (long)kk * 32768;            // [128][256]

    float p1[2][4][4];
    #pragma unroll
    for (int i = 0; i < 2; i++)
        #pragma unroll
        for (int j = 0; j < 4; j++)
            #pragma unroll
            for (int q = 0; q < 4; q++) p1[i][j][q] = 0.f;

    uint32_t* Ah = smu + 18432;
    uint32_t* Al = smu + 20736;
    uint32_t* Bh = smu + 23040;
    uint32_t* Bl = smu + 27648;

    for (int kc = 0; kc < 8; kc++) {
        float4 rc[2], rw[4];
        #pragma unroll
        for (int l = 0; l < 2; l++) {
            int u = tid + l*256, r = u >> 3, c4 = u & 7;
            rc[l] = *(const float4*)(Cg + (long)r*256 + kc*32 + c4*4);
        }
        #pragma unroll
        for (int l = 0; l < 4; l++) {
            int u = tid + l*256, r = u >> 3, c4 = u & 7;
            rw[l] = *(const float4*)(Wg + (long)r*256 + kc*32 + c4*4);
        }
        __syncthreads();   // prior MMA reads done before overwrite
        #pragma unroll
        for (int l = 0; l < 2; l++) {
            int u = tid + l*256, r = u >> 3, c4 = u & 7;
            uint4 h, lo; cvt_hl(rc[l], h, lo);
            *(uint4*)(Ah + r*36 + c4*4) = h;
            *(uint4*)(Al + r*36 + c4*4) = lo;
        }
        #pragma unroll
        for (int l = 0; l < 4; l++) {
            int u = tid + l*256, r = u >> 3, c4 = u & 7;
            uint4 h, lo; cvt_hl(rw[l], h, lo);
            *(uint4*)(Bh + r*36 + c4*4) = h;
            *(uint4*)(Bl + r*36 + c4*4) = lo;
        }
        __syncthreads();
        #pragma unroll
        for (int ks = 0; ks < 4; ks++) {
            int k = ks * 8;
            uint32_t ah[2][4], al[2][4];
            #pragma unroll
            for (int i = 0; i < 2; i++) {
                int r0 = wm*32 + i*16 + gid;
                ah[i][0] = Ah[r0*36 + k + tig];
                ah[i][1] = Ah[(r0+8)*36 + k + tig];
                ah[i][2] = Ah[r0*36 + k + tig + 4];
                ah[i][3] = Ah[(r0+8)*36 + k + tig + 4];
                al[i][0] = Al[r0*36 + k + tig];
                al[i][1] = Al[(r0+8)*36 + k + tig];
                al[i][2] = Al[r0*36 + k + tig + 4];
                al[i][3] = Al[(r0+8)*36 + k + tig + 4];
            }
            #pragma unroll
            for (int j = 0; j < 4; j++) {
                int n = wn*32 + j*8 + gid;
                uint32_t bh[2], bl[2];
                bh[0] = Bh[n*36 + k + tig];
                bh[1] = Bh[n*36 + k + tig + 4];
                bl[0] = Bl[n*36 + k + tig];
                bl[1] = Bl[n*36 + k + tig + 4];
                #pragma unroll
                for (int i = 0; i < 2; i++) {
                    mma8(p1[i][j], ah[i], bh);
                    mma8(p1[i][j], ah[i], bl);
                    mma8(p1[i][j], al[i], bh);
                }
            }
        }
    }

    // bias + row-norm
    float bb[4][2];
    #pragma unroll
    for (int j = 0; j < 4; j++) {
        int colb = wn*32 + j*8 + tig*2;
        bb[j][0] = Wkb[kk*128 + colb];
        bb[j][1] = Wkb[kk*128 + colb + 1];
    }
    #pragma unroll
    for (int i = 0; i < 2; i++)
        #pragma unroll
        for (int j = 0; j < 4; j++) {
            p1[i][j][0] += bb[j][0]; p1[i][j][1] += bb[j][1];
            p1[i][j][2] += bb[j][0]; p1[i][j][3] += bb[j][1];
        }

    float* rs   = (float*)(smu + 18432);     // [64][17]
    float* rinv = (float*)(smu + 18432 + 1088);
    __syncthreads();   // done with phase-1 staging reads
    #pragma unroll
    for (int i = 0; i < 2; i++) {
        float ss0 = 0.f, ss1 = 0.f;
        #pragma unroll
        for (int j = 0; j < 4; j++) {
            ss0 += p1[i][j][0]*p1[i][j][0] + p1[i][j][1]*p1[i][j][1];
            ss1 += p1[i][j][2]*p1[i][j][2] + p1[i][j][3]*p1[i][j][3];
        }
        int r0 = wm*32 + i*16 + gid;
        rs[r0*17 + wn*4 + tig]     = ss0;
        rs[(r0+8)*17 + wn*4 + tig] = ss1;
    }
    __syncthreads();
    if (tid < 64) {
        float ss = 0.f;
        #pragma unroll
        for (int x = 0; x < 16; x++) ss += rs[tid*17 + x];
        rinv[tid] = 10.f / fmaxf(sqrtf(ss), 1e-12f);
    }
    __syncthreads();
    // read scale factors into regs (rinv lives in the Z-buffer area)
    float sc[2][2];
    #pragma unroll
    for (int i = 0; i < 2; i++) {
        int r0 = wm*32 + i*16 + gid;
        sc[i][0] = rinv[r0];
        sc[i][1] = rinv[r0 + 8];
    }
    __syncthreads();   // all rinv reads done before Z stores overwrite

    // stage scaled U hi/lo: chunk layout Uh[(d>>5)*2304 + r*36 + (d&31)]
    #pragma unroll
    for (int i = 0; i < 2; i++)
        #pragma unroll
        for (int j = 0; j < 4; j++)
            #pragma unroll
            for (int q = 0; q < 4; q++) {
                int r = wm*32 + i*16 + gid + ((q >= 2) ? 8 : 0);
                int d = wn*32 + j*8 + tig*2 + (q & 1);
                float v = p1[i][j][q] * sc[i][q >> 1];
                uint32_t h = f2tf(v);
                uint32_t lo = f2tf(v - __uint_as_float(h));
                int off = (d >> 5)*2304 + r*36 + (d & 31);
                smu[off]        = h;
                smu[9216 + off] = lo;
            }

    // ================= phase 2: logits =================
    const float* Zg = g_z + (long)b * 32768;

    float c[2][8][4];
    #pragma unroll
    for (int i = 0; i < 2; i++)
        #pragma unroll
        for (int j = 0; j < 8; j++)
            #pragma unroll
            for (int q = 0; q < 4; q++) c[i][j][q] = 0.f;

    float4 rz[8];
    #pragma unroll
    for (int l = 0; l < 8; l++) {
        int u = tid + l*256, r = u >> 3, c4 = u & 7;
        rz[l] = *(const float4*)(Zg + (long)r*128 + c4*4);
    }
    __syncthreads();   // U staging writes done; rinv reads done
    {
        uint32_t* Zh = smu + 18432;
        uint32_t* Zl = smu + 27648;
        #pragma unroll
        for (int l = 0; l < 8; l++) {
            int u = tid + l*256, r = u >> 3, c4 = u & 7;
            uint4 h, lo; cvt_hl(rz[l], h, lo);
            *(uint4*)(Zh + r*36 + c4*4) = h;
            *(uint4*)(Zl + r*36 + c4*4) = lo;
        }
    }
    __syncthreads();

    #pragma unroll
    for (int kc = 0; kc < 4; kc++) {
        uint32_t* Zh = smu + 18432 + (kc & 1)*18432;
        uint32_t* Zl = Zh + 9216;
        const uint32_t* Uh = smu + kc*2304;
        const uint32_t* Ul = smu + 9216 + kc*2304;
        bool nxt = (kc < 3);
        if (nxt) {
            int k0 = (kc + 1) * 32;
            #pragma unroll
            for (int l = 0; l < 8; l++) {
                int u = tid + l*256, r = u >> 3, c4 = u & 7;
                rz[l] = *(const float4*)(Zg + (long)r*128 + k0 + c4*4);
            }
        }
        #pragma unroll
        for (int ks = 0; ks < 4; ks++) {
            int k = ks * 8;
            uint32_t ah[2][4], al[2][4];
            #pragma unroll
            for (int i = 0; i < 2; i++) {
                int r0 = wm*32 + i*16 + gid;
                ah[i][0] = Uh[r0*36 + k + tig];
                ah[i][1] = Uh[(r0+8)*36 + k + tig];
                ah[i][2] = Uh[r0*36 + k + tig + 4];
                ah[i][3] = Uh[(r0+8)*36 + k + tig + 4];
                al[i][0] = Ul[r0*36 + k + tig];
                al[i][1] = Ul[(r0+8)*36 + k + tig];
                al[i][2] = Ul[r0*36 + k + tig + 4];
                al[i][3] = Ul[(r0+8)*36 + k + tig + 4];
            }
            #pragma unroll
            for (int j = 0; j < 8; j++) {
                int n = wn*64 + j*8 + gid;
                uint32_t bh[2], bl[2];
                bh[0] = Zh[n*36 + k + tig];
                bh[1] = Zh[n*36 + k + tig + 4];
                bl[0] = Zl[n*36 + k + tig];
                bl[1] = Zl[n*36 + k + tig + 4];
                #pragma unroll
                for (int i = 0; i < 2; i++) {
                    mma8(c[i][j], ah[i], bh);
                    mma8(c[i][j], ah[i], bl);
                    mma8(c[i][j], al[i], bh);
                }
            }
        }
        if (nxt) {
            uint32_t* Znh = smu + 18432 + ((kc + 1) & 1)*18432;
            uint32_t* Znl = Znh + 9216;
            #pragma unroll
            for (int l = 0; l < 8; l++) {
                int u = tid + l*256, r = u >> 3, c4 = u & 7;
                uint4 h, lo; cvt_hl(rz[l], h, lo);
                *(uint4*)(Znh + r*36 + c4*4) = h;
                *(uint4*)(Znl + r*36 + c4*4) = lo;
            }
            __syncthreads();
        }
    }

    // fragment-level reductions
    float* redL = (float*)(smu + 18432);
    float* redM = redL + 256;
    float* redP = redM + 256;
    float* wred = redP + 256;
    __syncthreads();   // Z staging reads done before overlay

    #pragma unroll
    for (int i = 0; i < 2; i++) {
        #pragma unroll
        for (int sub = 0; sub < 2; sub++) {
            int rrow = wm*32 + i*16 + sub*8 + gid;
            int spos = t0 + rrow + kk + 1;
            float lsum = 0.f, nmax = -3.0e38f, pos = -3.0e38f;
            #pragma unroll
            for (int j = 0; j < 8; j++) {
                #pragma unroll
                for (int p = 0; p < 2; p++) {
                    int col = wn*64 + j*8 + tig*2 + p;
                    float l = c[i][j][sub*2 + p];
                    lsum += __expf(l);
                    if (col == spos) pos = l;
                    else             nmax = fmaxf(nmax, l);
                }
            }
            #pragma unroll
            for (int o = 1; o <= 2; o <<= 1) {
                lsum += __shfl_xor_sync(0xffffffffu, lsum, o);
                nmax = fmaxf(nmax, __shfl_xor_sync(0xffffffffu, nmax, o));
                pos  = fmaxf(pos,  __shfl_xor_sync(0xffffffffu, pos,  o));
            }
            if (tig == 0) {
                redL[wn*64 + rrow] = lsum;
                redM[wn*64 + rrow] = nmax;
                redP[wn*64 + rrow] = pos;
            }
        }
    }
    __syncthreads();

    float loss_tot = 0.f, acc_tot = 0.f;
    if (tid < 64) {
        float ls = redL[tid] + redL[64+tid] + redL[128+tid] + redL[192+tid];
        float nm = fmaxf(fmaxf(redM[tid], redM[64+tid]), fmaxf(redM[128+tid], redM[192+tid]));
        float ps = fmaxf(fmaxf(redP[tid], redP[64+tid]), fmaxf(redP[128+tid], redP[192+tid]));
        int t = t0 + tid;
        if (t < TP) {
            loss_tot = logf(ls) - ps;
            acc_tot  = (ps >= nm) ? 1.f : 0.f;
        }
    }
    if (wid < 2) {
        #pragma unroll
        for (int o = 16; o; o >>= 1) {
            loss_tot += __shfl_xor_sync(0xffffffffu, loss_tot, o);
            acc_tot  += __shfl_xor_sync(0xffffffffu, acc_tot,  o);
        }
        if (lane == 0) { wred[wid*2] = loss_tot; wred[wid*2+1] = acc_tot; }
    }
    __syncthreads();
    if (tid == 0) {
        long bid = ((long)kk*128 + b)*4 + tile;
        g_part[bid*2]   = wred[0] + wred[2];
        g_part[bid*2+1] = wred[1] + wred[3];
    }
}

// ---------------- GRU v6 (unchanged from R12) ----------------------------
__global__ __launch_bounds__(256, 1) __cluster_dims__(8, 1, 1)
void gru6(const float* __restrict__ Whh, const float* __restrict__ bhh)
{
    extern __shared__ float s[];
    float* hb = s;                         // [2][2048]

    int tid  = threadIdx.x;
    int rank = blockIdx.x & 7;
    int cl   = blockIdx.x >> 3;
    int co   = rank * 32;
    int b0   = cl * 8;
    int c    = tid >> 3, ks = tid & 7;

    unsigned long long w0r[16], w1r[16], w2r[16];
    {
        const float* p0 = Whh + ((long)(0*256 + co + c))*256 + ks*32;
        const float* p1 = Whh + ((long)(1*256 + co + c))*256 + ks*32;
        const float* p2 = Whh + ((long)(2*256 + co + c))*256 + ks*32;
        #pragma unroll
        for (int i = 0; i < 16; i++) {
            w0r[i] = *(const unsigned long long*)(p0 + i*2);
            w1r[i] = *(const unsigned long long*)(p1 + i*2);
            w2r[i] = *(const unsigned long long*)(p2 + i*2);
        }
    }
    float bhr0 = bhh[co + c], bhr1 = bhh[256 + co + c], bhr2 = bhh[512 + co + c];

    for (int i = tid; i < 2*2048; i += 256) hb[i] = 0.f;

    const float* gxp = g_gx + ((long)(b0 + ks) * 256) * 768 + co + c;
    float*       cp  = g_c  + ((long)(b0 + ks) * 256) * 256 + co + c;
    int kg = co + c;
    int slot = ((ks*8 + ((kg >> 2) & 7))*8 + (kg >> 5))*4 + (kg & 3);
    uint32_t ladr = s2u(hb) + (uint32_t)(slot * 4);
    uint32_t radr[8];
    #pragma unroll
    for (int r = 0; r < 8; r++) radr[r] = mapa_u32(ladr, r);

    float h_old = 0.f;
    float xr = gxp[0], xz = gxp[256], xn = gxp[512];

    __syncthreads();
    asm volatile("barrier.cluster.arrive.aligned;" ::: "memory");
    asm volatile("barrier.cluster.wait.aligned;"   ::: "memory");

    for (int t = 0; t < 256; t++) {
        int p = t & 1, pn = p ^ 1;
        float xr_n = 0.f, xz_n = 0.f, xn_n = 0.f;
        if (t < 255) {
            const float* gq = gxp + (long)(t + 1) * 768;
            xr_n = gq[0]; xz_n = gq[256]; xn_n = gq[512];
        }

        const float* hp = hb + p*2048 + ks*4;
        float sg0[8], sg1[8], sg2[8];
        #pragma unroll
        for (int b = 0; b < 8; b++) {
            const float* hq = hp + b*256;
            unsigned long long a0 = 0ULL, a1 = 0ULL, a2 = 0ULL;
            #pragma unroll
            for (int j4 = 0; j4 < 8; j4++) {
                ulonglong2 h4 = *(const ulonglong2*)(hq + j4*32);
                FMA2(a0, w0r[j4*2], h4.x); FMA2(a0, w0r[j4*2+1], h4.y);
                FMA2(a1, w1r[j4*2], h4.x); FMA2(a1, w1r[j4*2+1], h4.y);
                FMA2(a2, w2r[j4*2], h4.x); FMA2(a2, w2r[j4*2+1], h4.y);
            }
            sg0[b] = pairsum(a0); sg1[b] = pairsum(a1); sg2[b] = pairsum(a2);
        }

        float t0g[4], t1g[4], t2g[4];
        bool hi4 = (ks & 4) != 0;
        #pragma unroll
        for (int i = 0; i < 4; i++) {
            float s0 = hi4 ? sg0[i] : sg0[i+4];
            float k0 = hi4 ? sg0[i+4] : sg0[i];
            t0g[i] = k0 + __shfl_xor_sync(0xffffffffu, s0, 4);
            float s1 = hi4 ? sg1[i] : sg1[i+4];
            float k1 = hi4 ? sg1[i+4] : sg1[i];
            t1g[i] = k1 + __shfl_xor_sync(0xffffffffu, s1, 4);
            float s2 = hi4 ? sg2[i] : sg2[i+4];
            float k2 = hi4 ? sg2[i+4] : sg2[i];
            t2g[i] = k2 + __shfl_xor_sync(0xffffffffu, s2, 4);
        }
        float u0g[2], u1g[2], u2g[2];
        bool hi2 = (ks & 2) != 0;
        #pragma unroll
        for (int i = 0; i < 2; i++) {
            float s0 = hi2 ? t0g[i] : t0g[i+2];
            float k0 = hi2 ? t0g[i+2] : t0g[i];
            u0g[i] = k0 + __shfl_xor_sync(0xffffffffu, s0, 2);
            float s1 = hi2 ? t1g[i] : t1g[i+2];
            float k1 = hi2 ? t1g[i+2] : t1g[i];
            u1g[i] = k1 + __shfl_xor_sync(0xffffffffu, s1, 2);
            float s2 = hi2 ? t2g[i] : t2g[i+2];
            float k2 = hi2 ? t2g[i+2] : t2g[i];
            u2g[i] = k2 + __shfl_xor_sync(0xffffffffu, s2, 2);
        }
        bool hi1 = (ks & 1) != 0;
        float s0 = hi1 ? u0g[0] : u0g[1];
        float k0 = hi1 ? u0g[1] : u0g[0];
        float hr = k0 + __shfl_xor_sync(0xffffffffu, s0, 1) + bhr0;
        float s1 = hi1 ? u1g[0] : u1g[1];
        float k1 = hi1 ? u1g[1] : u1g[0];
        float hz = k1 + __shfl_xor_sync(0xffffffffu, s1, 1) + bhr1;
        float s2 = hi1 ? u2g[0] : u2g[1];
        float k2 = hi1 ? u2g[1] : u2g[0];
        float hn = k2 + __shfl_xor_sync(0xffffffffu, s2, 1) + bhr2;

        float rg = fsig(xr + hr);
        float zg = fsig(xz + hz);
        float ng = ftanh(xn + rg*hn);
        float hnew = (1.f - zg)*ng + zg*h_old;
        h_old = hnew;

        uint32_t off = (uint32_t)(pn * 8192);
        #pragma unroll
        for (int r = 0; r < 8; r++) st_cluster_f32(radr[r] + off, hnew);
        cp[(long)t*256] = hnew;

        xr = xr_n; xz = xz_n; xn = xn_n;

        asm volatile("barrier.cluster.arrive.aligned;" ::: "memory");
        asm volatile("barrier.cluster.wait.aligned;"   ::: "memory");
    }
}

// ---------------- final reduction ---------------------------------------
__global__ void final_kernel(float* __restrict__ out)
{
    __shared__ float sl[256], sa[256];
    int tid = threadIdx.x;
    float L = 0.f, A = 0.f;
    for (int i = tid; i < 6144; i += 256) { L += g_part[i*2]; A += g_part[i*2+1]; }
    sl[tid] = L; sa[tid] = A;
    __syncthreads();
    for (int o = 128; o; o >>= 1) {
        if (tid < o) { sl[tid] += sl[tid+o]; sa[tid] += sa[tid+o]; }
        __syncthreads();
    }
    if (tid == 0) {
        out[0] = sl[0] / (float)NROWS_L;
        out[1] = sa[0] / (float)NROWS_L * 100.f;
    }
}

// ---------------- copy z and c into d_out (8B-aligned dst) ---------------
__global__ void copyout_kernel(float* __restrict__ out)
{
    long i = (long)blockIdx.x * 256 + threadIdx.x;
    float2* dst = (float2*)(out + 2);
    const long NZ2 = 2097152;
    const long NC2 = 4194304;
    if (i < NZ2) {
        dst[i] = ((const float2*)g_z)[i];
    } else if (i < NZ2 + NC2) {
        dst[i] = ((const float2*)g_c)[i - NZ2];
    }
}

// ---------------- host launcher ------------------------------------------
extern "C" void kernel_launch(void* const* d_in, const int* in_sizes, int n_in,
                              void* d_out, int out_size)
{
    const float* rr  = (const float*)d_in[0];
    const float* w1  = (const float*)d_in[1];
    const float* b1  = (const float*)d_in[2];
    const float* w2  = (const float*)d_in[3];
    const float* b2  = (const float*)d_in[4];
    const float* Wih = (const float*)d_in[5];
    const float* Whh = (const float*)d_in[6];
    const float* bih = (const float*)d_in[7];
    const float* bhh = (const float*)d_in[8];
    const float* Wkw = (const float*)d_in[9];
    const float* Wkb = (const float*)d_in[10];

    float* out = (float*)d_out;

    float *pz, *pc, *ph1, *pgx, *pw1T, *pw2T;
    cudaGetSymbolAddress((void**)&pz,   g_z);
    cudaGetSymbolAddress((void**)&pc,   g_c);
    cudaGetSymbolAddress((void**)&ph1,  g_h1);
    cudaGetSymbolAddress((void**)&pgx,  g_gx);
    cudaGetSymbolAddress((void**)&pw1T, g_w1T);
    cudaGetSymbolAddress((void**)&pw2T, g_w2T);

    cudaFuncSetAttribute(fused_logits, cudaFuncAttributeMaxDynamicSharedMemorySize, FUS_SMEM);
    cudaFuncSetAttribute(gru6,         cudaFuncAttributeMaxDynamicSharedMemorySize, GRU6_SMEM);
    cudaFuncSetAttribute(mma_gemm,     cudaFuncAttributeMaxDynamicSharedMemorySize, GEMM_SMEM);

    // 0-1. weight transposes
    prep_a<<<256, 256>>>(w1, w2);
    prep_b<<<1536, 256>>>(Wkw);
    // 2. encoder layer 1 (relu)
    mma_gemm<<<dim3(2, 256, 1), 256, GEMM_SMEM>>>(
        rr, pw1T, b1, ph1, N_BT, 256, 256, 1, 0, 0, 0, 0);
    // 3. encoder layer 2 -> normalized z (mode 2)
    mma_gemm<<<dim3(1, 256, 1), 256, GEMM_SMEM>>>(
        ph1, pw2T, b2, pz, N_BT, 128, 256, 0, 2, 0, 0, 0);
    // 4. gx = z @ W_ih^T + b_ih
    mma_gemm<<<dim3(6, 256, 1), 256, GEMM_SMEM>>>(
        pz, Wih, bih, pgx, N_BT, 768, 128, 0, 0, 0, 0, 0);
    // 5. GRU v6
    gru6<<<128, 256, GRU6_SMEM>>>(Whh, bhh);
    // 6. fused U-GEMM + row-norm + logits + reductions
    fused_logits<<<dim3(4, 128, 12), 256, FUS_SMEM>>>(Wkb);
    // 7. final loss/accuracy
    final_kernel<<<1, 256>>>(out);
    // 8. copy z_seq and c_seq into d_out
    copyout_kernel<<<24576, 256>>>(out);
}

// round 14
// speedup vs baseline: 1.0984x; 1.0984x over previous
#include <cuda_runtime.h>
#include <math.h>
#include <stdint.h>

// B=128, T=256, W=256, D=128, C=256, K=12, Tp=244, TEMP=0.1
#define N_BT     32768
#define TP       244
#define NROWS_L  374784
// gemm smem (single buffer): Ah/Al/Bh/Bl 4x4608 + bias 128 words
#define GEMM_SMEM ((4*4608 + 128)*4)
// logits smem (single buffer): Uh/Ul 2x2304 + Zh/Zl 2x9216 + red 832 words
#define LOG_SMEM  ((4608 + 18432 + 832)*4)
// GRU6 smem
#define GRU6_SMEM (2*2048*4)

// ---------------- packed f32x2 helpers -----------------------------------
#define FMA2(d,a,b) asm("fma.rn.f32x2 %0, %1, %2, %0;" : "+l"(d) : "l"(a), "l"(b))
__device__ __forceinline__ void unpack2(unsigned long long v, float& lo, float& hi) {
    asm("mov.b64 {%0, %1}, %2;" : "=f"(lo), "=f"(hi) : "l"(v));
}
__device__ __forceinline__ float pairsum(unsigned long long v) {
    float a, b; unpack2(v, a, b); return a + b;
}
__device__ __forceinline__ uint32_t s2u(const void* p) {
    uint32_t a; asm("{ .reg .u64 t; cvta.to.shared.u64 t, %1; cvt.u32.u64 %0, t; }" : "=r"(a) : "l"(p));
    return a;
}
__device__ __forceinline__ uint32_t mapa_u32(uint32_t addr, uint32_t rank) {
    uint32_t r; asm("mapa.shared::cluster.u32 %0, %1, %2;" : "=r"(r) : "r"(addr), "r"(rank));
    return r;
}
__device__ __forceinline__ void st_cluster_f32(uint32_t addr, float v) {
    asm volatile("st.shared::cluster.f32 [%0], %1;" :: "r"(addr), "f"(v) : "memory");
}
__device__ __forceinline__ float fsig(float x)  { return 1.f / (1.f + __expf(-x)); }
__device__ __forceinline__ float ftanh(float x) { return 1.f - 2.f / (1.f + __expf(2.f*x)); }

// ---------------- tf32 mma helpers ---------------------------------------
__device__ __forceinline__ uint32_t f2tf(float x) {
    uint32_t r; asm("cvt.rna.tf32.f32 %0, %1;" : "=r"(r) : "f"(x)); return r;
}
__device__ __forceinline__ void cvt_hl(float4 x, uint4& h, uint4& l) {
    h.x = f2tf(x.x); l.x = f2tf(x.x - __uint_as_float(h.x));
    h.y = f2tf(x.y); l.y = f2tf(x.y - __uint_as_float(h.y));
    h.z = f2tf(x.z); l.z = f2tf(x.z - __uint_as_float(h.z));
    h.w = f2tf(x.w); l.w = f2tf(x.w - __uint_as_float(h.w));
}
__device__ __forceinline__ void mma8(float* c, const uint32_t* a, const uint32_t* b) {
    asm volatile("mma.sync.aligned.m16n8k8.row.col.f32.tf32.tf32.f32 "
        "{%0,%1,%2,%3}, {%4,%5,%6,%7}, {%8,%9}, {%0,%1,%2,%3};"
        : "+f"(c[0]), "+f"(c[1]), "+f"(c[2]), "+f"(c[3])
        : "r"(a[0]), "r"(a[1]), "r"(a[2]), "r"(a[3]), "r"(b[0]), "r"(b[1]));
}

// ---------------- scratch ------------------------------------------------
__device__ __align__(16) float g_z   [4194304];   // [32768,128] normalized z
__device__ __align__(16) float g_c   [8388608];   // [32768,256] c_seq
__device__ __align__(16) float g_h1  [8388608];   // [32768,256]
__device__ __align__(16) float g_gx  [25165824];  // [32768,768]
__device__ __align__(16) float g_U   [50331648];  // [12,32768,128] rows scaled by 10/||.||
__device__ __align__(16) float g_w1T [65536];
__device__ __align__(16) float g_w2T [32768];
__device__ __align__(16) float g_WkT [393216];
__device__ __align__(16) float g_part[12288];

// ---------------- prep: transposes ---------------------------------------
__global__ void prep_a(const float* __restrict__ w1, const float* __restrict__ w2)
{
    long i = (long)blockIdx.x * 256 + threadIdx.x;
    if (i < 65536) {
        int n = (int)(i >> 8), k = (int)(i & 255);
        g_w1T[n*256 + k] = w1[k*256 + n];
    }
    if (i < 32768) {
        int n = (int)(i >> 8), k = (int)(i & 255);
        g_w2T[n*256 + k] = w2[k*128 + n];
    }
}
__global__ void prep_b(const float* __restrict__ wk)
{
    long i = (long)blockIdx.x * 256 + threadIdx.x;
    if (i < 393216) {
        long kk = i / 32768; long r = i % 32768;
        int d = (int)(r >> 8), c = (int)(r & 255);
        g_WkT[kk*32768 + d*256 + c] = wk[kk*32768 + c*128 + d];
    }
}

// ---------------- 3xTF32 mma.sync NT-GEMM (single-buffer, 2 CTAs/SM) -----
// C = A @ B^T + bias. Block tile 128x128, warp tile 64x32, K chunks of 32.
// mode 0: plain(+relu); 1: rows *= 10/max(||r||,eps); 2: rows *= 1/..; need N==128.
__global__ __launch_bounds__(256, 2) void mma_gemm(
    const float* __restrict__ A, const float* __restrict__ Bm,
    const float* __restrict__ bias, float* __restrict__ Cm,
    int M, int N, int K, int relu, int mode,
    long sB, long sBias, long sC)
{
    extern __shared__ uint32_t smu[];
    uint32_t* Ah = smu;                 // 4608
    uint32_t* Al = smu + 4608;
    uint32_t* Bh = smu + 9216;
    uint32_t* Bl = smu + 13824;
    float* sbias = (float*)(smu + 18432);
    float* rs    = (float*)smu;         // overlay [128][17] (epilogue only)
    float* rinv  = (float*)(smu + 2176);

    const float* Bz = Bm  + (long)blockIdx.z * sB;
    const float* bz = bias + (long)blockIdx.z * sBias;
    float*       Cz = Cm  + (long)blockIdx.z * sC;
    int m0 = blockIdx.y * 128, n0 = blockIdx.x * 128;

    int tid = threadIdx.x;
    int wid = tid >> 5, lane = tid & 31;
    int wm = wid >> 2, wn = wid & 3;
    int gid = lane >> 2, tig = lane & 3;

    if (tid < 128) sbias[tid] = bz[n0 + tid];

    const float* Ag = A  + (long)m0 * K;
    const float* Bg = Bz + (long)n0 * K;

    float c[4][4][4];
    #pragma unroll
    for (int i = 0; i < 4; i++)
        #pragma unroll
        for (int j = 0; j < 4; j++)
            #pragma unroll
            for (int q = 0; q < 4; q++) c[i][j][q] = 0.f;

    int NC = K >> 5;
    for (int kc = 0; kc < NC; kc++) {
        int k0 = kc * 32;
        __syncthreads();   // prior chunk's mma reads complete
        #pragma unroll
        for (int l = 0; l < 4; l++) {
            int u = tid + l*256, r = u >> 3, c4 = u & 7;
            float4 va = *(const float4*)(Ag + (long)r*K + k0 + c4*4);
            float4 vb = *(const float4*)(Bg + (long)r*K + k0 + c4*4);
            uint4 h, lo;
            cvt_hl(va, h, lo);
            *(uint4*)(Ah + r*36 + c4*4) = h;
            *(uint4*)(Al + r*36 + c4*4) = lo;
            cvt_hl(vb, h, lo);
            *(uint4*)(Bh + r*36 + c4*4) = h;
            *(uint4*)(Bl + r*36 + c4*4) = lo;
        }
        __syncthreads();
        #pragma unroll
        for (int ks = 0; ks < 4; ks++) {
            int k = ks * 8;
            uint32_t ah[4][4], al[4][4];
            #pragma unroll
            for (int i = 0; i < 4; i++) {
                int r0 = wm*64 + i*16 + gid;
                ah[i][0] = Ah[r0*36 + k + tig];
                ah[i][1] = Ah[(r0+8)*36 + k + tig];
                ah[i][2] = Ah[r0*36 + k + tig + 4];
                ah[i][3] = Ah[(r0+8)*36 + k + tig + 4];
                al[i][0] = Al[r0*36 + k + tig];
                al[i][1] = Al[(r0+8)*36 + k + tig];
                al[i][2] = Al[r0*36 + k + tig + 4];
                al[i][3] = Al[(r0+8)*36 + k + tig + 4];
            }
            #pragma unroll
            for (int j = 0; j < 4; j++) {
                int n = wn*32 + j*8 + gid;
                uint32_t bh[2], bl[2];
                bh[0] = Bh[n*36 + k + tig];
                bh[1] = Bh[n*36 + k + tig + 4];
                bl[0] = Bl[n*36 + k + tig];
                bl[1] = Bl[n*36 + k + tig + 4];
                #pragma unroll
                for (int i = 0; i < 4; i++) {
                    mma8(c[i][j], ah[i], bh);
                    mma8(c[i][j], ah[i], bl);
                    mma8(c[i][j], al[i], bh);
                }
            }
        }
    }

    // epilogue: bias
    #pragma unroll
    for (int i = 0; i < 4; i++)
        #pragma unroll
        for (int j = 0; j < 4; j++) {
            int colb = wn*32 + j*8 + tig*2;
            c[i][j][0] += sbias[colb]; c[i][j][1] += sbias[colb+1];
            c[i][j][2] += sbias[colb]; c[i][j][3] += sbias[colb+1];
        }

    if (mode == 0) {
        #pragma unroll
        for (int i = 0; i < 4; i++) {
            int r0 = m0 + wm*64 + i*16 + gid;
            #pragma unroll
            for (int j = 0; j < 4; j++) {
                int colb = n0 + wn*32 + j*8 + tig*2;
                float2 v0 = make_float2(c[i][j][0], c[i][j][1]);
                float2 v1 = make_float2(c[i][j][2], c[i][j][3]);
                if (relu) {
                    v0.x = fmaxf(v0.x, 0.f); v0.y = fmaxf(v0.y, 0.f);
                    v1.x = fmaxf(v1.x, 0.f); v1.y = fmaxf(v1.y, 0.f);
                }
                *(float2*)(Cz + (long)r0*N + colb)     = v0;
                *(float2*)(Cz + (long)(r0+8)*N + colb) = v1;
            }
        }
    } else {
        __syncthreads();   // done with staging reads; overlay rs
        #pragma unroll
        for (int i = 0; i < 4; i++) {
            float ss0 = 0.f, ss1 = 0.f;
            #pragma unroll
            for (int j = 0; j < 4; j++) {
                ss0 += c[i][j][0]*c[i][j][0] + c[i][j][1]*c[i][j][1];
                ss1 += c[i][j][2]*c[i][j][2] + c[i][j][3]*c[i][j][3];
            }
            int r0 = wm*64 + i*16 + gid;
            rs[r0*17 + wn*4 + tig]     = ss0;
            rs[(r0+8)*17 + wn*4 + tig] = ss1;
        }
        __syncthreads();
        if (tid < 128) {
            float ss = 0.f;
            #pragma unroll
            for (int x = 0; x < 16; x++) ss += rs[tid*17 + x];
            float inv = 1.f / fmaxf(sqrtf(ss), 1e-12f);
            if (mode == 1) inv *= 10.f;
            rinv[tid] = inv;
        }
        __syncthreads();
        #pragma unroll
        for (int i = 0; i < 4; i++) {
            int rr = wm*64 + i*16 + gid;
            float sc0 = rinv[rr], sc1 = rinv[rr+8];
            int r0 = m0 + rr;
            #pragma unroll
            for (int j = 0; j < 4; j++) {
                int colb = n0 + wn*32 + j*8 + tig*2;
                *(float2*)(Cz + (long)r0*N + colb) =
                    make_float2(c[i][j][0]*sc0, c[i][j][1]*sc0);
                *(float2*)(Cz + (long)(r0+8)*N + colb) =
                    make_float2(c[i][j][2]*sc1, c[i][j][3]*sc1);
            }
        }
    }
}

// ---------------- logits via 3xTF32 mma (single-buffer, 2 CTAs/SM) -------
// grid (4 t-tiles, 128 b, 12 k); block 256. Block tile 64(t) x 256(s) x 128(d).
__global__ __launch_bounds__(256, 2) void logits_mma()
{
    extern __shared__ uint32_t smu[];
    uint32_t* Uh = smu;                 // 2304
    uint32_t* Ul = smu + 2304;
    uint32_t* Zh = smu + 4608;          // 9216
    uint32_t* Zl = smu + 13824;
    float* redL = (float*)(smu + 23040);
    float* redM = redL + 256;
    float* redP = redM + 256;
    float* wred = redP + 256;

    int tile = blockIdx.x, b = blockIdx.y, kk = blockIdx.z;
    int t0 = tile * 64;
    int tid = threadIdx.x;
    int wid = tid >> 5, lane = tid & 31;
    int wm = wid >> 2, wn = wid & 3;
    int gid = lane >> 2, tig = lane & 3;

    const float* Ug = g_U + ((long)kk*32768 + (long)b*256 + t0) * 128;
    const float* Zg = g_z + (long)b * 32768;

    float c[2][8][4];
    #pragma unroll
    for (int i = 0; i < 2; i++)
        #pragma unroll
        for (int j = 0; j < 8; j++)
            #pragma unroll
            for (int q = 0; q < 4; q++) c[i][j][q] = 0.f;

    #pragma unroll
    for (int kc = 0; kc < 4; kc++) {
        int k0 = kc * 32;
        __syncthreads();
        #pragma unroll
        for (int l = 0; l < 8; l++) {
            int u = tid + l*256, r = u >> 3, c4 = u & 7;
            float4 v = *(const float4*)(Zg + (long)r*128 + k0 + c4*4);
            uint4 h, lo; cvt_hl(v, h, lo);
            *(uint4*)(Zh + r*36 + c4*4) = h;
            *(uint4*)(Zl + r*36 + c4*4) = lo;
        }
        #pragma unroll
        for (int l = 0; l < 2; l++) {
            int u = tid + l*256, r = u >> 3, c4 = u & 7;
            float4 v = *(const float4*)(Ug + (long)r*128 + k0 + c4*4);
            uint4 h, lo; cvt_hl(v, h, lo);
            *(uint4*)(Uh + r*36 + c4*4) = h;
            *(uint4*)(Ul + r*36 + c4*4) = lo;
        }
        __syncthreads();
        #pragma unroll
        for (int ks = 0; ks < 4; ks++) {
            int k = ks * 8;
            uint32_t ah[2][4], al[2][4];
            #pragma unroll
            for (int i = 0; i < 2; i++) {
                int r0 = wm*32 + i*16 + gid;
                ah[i][0] = Uh[r0*36 + k + tig];
                ah[i][1] = Uh[(r0+8)*36 + k + tig];
                ah[i][2] = Uh[r0*36 + k + tig + 4];
                ah[i][3] = Uh[(r0+8)*36 + k + tig + 4];
                al[i][0] = Ul[r0*36 + k + tig];
                al[i][1] = Ul[(r0+8)*36 + k + tig];
                al[i][2] = Ul[r0*36 + k + tig + 4];
                al[i][3] = Ul[(r0+8)*36 + k + tig + 4];
            }
            #pragma unroll
            for (int j = 0; j < 8; j++) {
                int n = wn*64 + j*8 + gid;
                uint32_t bh[2], bl[2];
                bh[0] = Zh[n*36 + k + tig];
                bh[1] = Zh[n*36 + k + tig + 4];
                bl[0] = Zl[n*36 + k + tig];
                bl[1] = Zl[n*36 + k + tig + 4];
                #pragma unroll
                for (int i = 0; i < 2; i++) {
                    mma8(c[i][j], ah[i], bh);
                    mma8(c[i][j], ah[i], bl);
                    mma8(c[i][j], al[i], bh);
                }
            }
        }
    }

    #pragma unroll
    for (int i = 0; i < 2; i++) {
        #pragma unroll
        for (int sub = 0; sub < 2; sub++) {
            int rrow = wm*32 + i*16 + sub*8 + gid;
            int spos = t0 + rrow + kk + 1;
            float lsum = 0.f, nmax = -3.0e38f, pos = -3.0e38f;
            #pragma unroll
            for (int j = 0; j < 8; j++) {
                #pragma unroll
                for (int p = 0; p < 2; p++) {
                    int col = wn*64 + j*8 + tig*2 + p;
                    float l = c[i][j][sub*2 + p];
                    lsum += __expf(l);
                    if (col == spos) pos = l;
                    else             nmax = fmaxf(nmax, l);
                }
            }
            #pragma unroll
            for (int o = 1; o <= 2; o <<= 1) {
                lsum += __shfl_xor_sync(0xffffffffu, lsum, o);
                nmax = fmaxf(nmax, __shfl_xor_sync(0xffffffffu, nmax, o));
                pos  = fmaxf(pos,  __shfl_xor_sync(0xffffffffu, pos,  o));
            }
            if (tig == 0) {
                redL[wn*64 + rrow] = lsum;
                redM[wn*64 + rrow] = nmax;
                redP[wn*64 + rrow] = pos;
            }
        }
    }
    __syncthreads();

    float loss_tot = 0.f, acc_tot = 0.f;
    if (tid < 64) {
        float ls = redL[tid] + redL[64+tid] + redL[128+tid] + redL[192+tid];
        float nm = fmaxf(fmaxf(redM[tid], redM[64+tid]), fmaxf(redM[128+tid], redM[192+tid]));
        float ps = fmaxf(fmaxf(redP[tid], redP[64+tid]), fmaxf(redP[128+tid], redP[192+tid]));
        int t = t0 + tid;
        if (t < TP) {
            loss_tot = logf(ls) - ps;
            acc_tot  = (ps >= nm) ? 1.f : 0.f;
        }
    }
    if (wid < 2) {
        #pragma unroll
        for (int o = 16; o; o >>= 1) {
            loss_tot += __shfl_xor_sync(0xffffffffu, loss_tot, o);
            acc_tot  += __shfl_xor_sync(0xffffffffu, acc_tot,  o);
        }
        if (lane == 0) { wred[wid*2] = loss_tot; wred[wid*2+1] = acc_tot; }
    }
    __syncthreads();
    if (tid == 0) {
        long bid = ((long)kk*128 + b)*4 + tile;
        g_part[bid*2]   = wred[0] + wred[2];
        g_part[bid*2+1] = wred[1] + wred[3];
    }
}

// ---------------- GRU v6 (unchanged) --------------------------------------
__global__ __launch_bounds__(256, 1) __cluster_dims__(8, 1, 1)
void gru6(const float* __restrict__ Whh, const float* __restrict__ bhh)
{
    extern __shared__ float s[];
    float* hb = s;                         // [2][2048]

    int tid  = threadIdx.x;
    int rank = blockIdx.x & 7;
    int cl   = blockIdx.x >> 3;
    int co   = rank * 32;
    int b0   = cl * 8;
    int c    = tid >> 3, ks = tid & 7;

    unsigned long long w0r[16], w1r[16], w2r[16];
    {
        const float* p0 = Whh + ((long)(0*256 + co + c))*256 + ks*32;
        const float* p1 = Whh + ((long)(1*256 + co + c))*256 + ks*32;
        const float* p2 = Whh + ((long)(2*256 + co + c))*256 + ks*32;
        #pragma unroll
        for (int i = 0; i < 16; i++) {
            w0r[i] = *(const unsigned long long*)(p0 + i*2);
            w1r[i] = *(const unsigned long long*)(p1 + i*2);
            w2r[i] = *(const unsigned long long*)(p2 + i*2);
        }
    }
    float bhr0 = bhh[co + c], bhr1 = bhh[256 + co + c], bhr2 = bhh[512 + co + c];

    for (int i = tid; i < 2*2048; i += 256) hb[i] = 0.f;

    const float* gxp = g_gx + ((long)(b0 + ks) * 256) * 768 + co + c;
    float*       cp  = g_c  + ((long)(b0 + ks) * 256) * 256 + co + c;
    int kg = co + c;
    int slot = ((ks*8 + ((kg >> 2) & 7))*8 + (kg >> 5))*4 + (kg & 3);
    uint32_t ladr = s2u(hb) + (uint32_t)(slot * 4);
    uint32_t radr[8];
    #pragma unroll
    for (int r = 0; r < 8; r++) radr[r] = mapa_u32(ladr, r);

    float h_old = 0.f;
    float xr = gxp[0], xz = gxp[256], xn = gxp[512];

    __syncthreads();
    asm volatile("barrier.cluster.arrive.aligned;" ::: "memory");
    asm volatile("barrier.cluster.wait.aligned;"   ::: "memory");

    for (int t = 0; t < 256; t++) {
        int p = t & 1, pn = p ^ 1;
        float xr_n = 0.f, xz_n = 0.f, xn_n = 0.f;
        if (t < 255) {
            const float* gq = gxp + (long)(t + 1) * 768;
            xr_n = gq[0]; xz_n = gq[256]; xn_n = gq[512];
        }

        const float* hp = hb + p*2048 + ks*4;
        float sg0[8], sg1[8], sg2[8];
        #pragma unroll
        for (int b = 0; b < 8; b++) {
            const float* hq = hp + b*256;
            unsigned long long a0 = 0ULL, a1 = 0ULL, a2 = 0ULL;
            #pragma unroll
            for (int j4 = 0; j4 < 8; j4++) {
                ulonglong2 h4 = *(const ulonglong2*)(hq + j4*32);
                FMA2(a0, w0r[j4*2], h4.x); FMA2(a0, w0r[j4*2+1], h4.y);
                FMA2(a1, w1r[j4*2], h4.x); FMA2(a1, w1r[j4*2+1], h4.y);
                FMA2(a2, w2r[j4*2], h4.x); FMA2(a2, w2r[j4*2+1], h4.y);
            }
            sg0[b] = pairsum(a0); sg1[b] = pairsum(a1); sg2[b] = pairsum(a2);
        }

        float t0g[4], t1g[4], t2g[4];
        bool hi4 = (ks & 4) != 0;
        #pragma unroll
        for (int i = 0; i < 4; i++) {
            float s0 = hi4 ? sg0[i] : sg0[i+4];
            float k0 = hi4 ? sg0[i+4] : sg0[i];
            t0g[i] = k0 + __shfl_xor_sync(0xffffffffu, s0, 4);
            float s1 = hi4 ? sg1[i] : sg1[i+4];
            float k1 = hi4 ? sg1[i+4] : sg1[i];
            t1g[i] = k1 + __shfl_xor_sync(0xffffffffu, s1, 4);
            float s2 = hi4 ? sg2[i] : sg2[i+4];
            float k2 = hi4 ? sg2[i+4] : sg2[i];
            t2g[i] = k2 + __shfl_xor_sync(0xffffffffu, s2, 4);
        }
        float u0g[2], u1g[2], u2g[2];
        bool hi2 = (ks & 2) != 0;
        #pragma unroll
        for (int i = 0; i < 2; i++) {
            float s0 = hi2 ? t0g[i] : t0g[i+2];
            float k0 = hi2 ? t0g[i+2] : t0g[i];
            u0g[i] = k0 + __shfl_xor_sync(0xffffffffu, s0, 2);
            float s1 = hi2 ? t1g[i] : t1g[i+2];
            float k1 = hi2 ? t1g[i+2] : t1g[i];
            u1g[i] = k1 + __shfl_xor_sync(0xffffffffu, s1, 2);
            float s2 = hi2 ? t2g[i] : t2g[i+2];
            float k2 = hi2 ? t2g[i+2] : t2g[i];
            u2g[i] = k2 + __shfl_xor_sync(0xffffffffu, s2, 2);
        }
        bool hi1 = (ks & 1) != 0;
        float s0 = hi1 ? u0g[0] : u0g[1];
        float k0 = hi1 ? u0g[1] : u0g[0];
        float hr = k0 + __shfl_xor_sync(0xffffffffu, s0, 1) + bhr0;
        float s1 = hi1 ? u1g[0] : u1g[1];
        float k1 = hi1 ? u1g[1] : u1g[0];
        float hz = k1 + __shfl_xor_sync(0xffffffffu, s1, 1) + bhr1;
        float s2 = hi1 ? u2g[0] : u2g[1];
        float k2 = hi1 ? u2g[1] : u2g[0];
        float hn = k2 + __shfl_xor_sync(0xffffffffu, s2, 1) + bhr2;

        float rg = fsig(xr + hr);
        float zg = fsig(xz + hz);
        float ng = ftanh(xn + rg*hn);
        float hnew = (1.f - zg)*ng + zg*h_old;
        h_old = hnew;

        uint32_t off = (uint32_t)(pn * 8192);
        #pragma unroll
        for (int r = 0; r < 8; r++) st_cluster_f32(radr[r] + off, hnew);
        cp[(long)t*256] = hnew;

        xr = xr_n; xz = xz_n; xn = xn_n;

        asm volatile("barrier.cluster.arrive.aligned;" ::: "memory");
        asm volatile("barrier.cluster.wait.aligned;"   ::: "memory");
    }
}

// ---------------- final reduction ---------------------------------------
__global__ void final_kernel(float* __restrict__ out)
{
    __shared__ float sl[256], sa[256];
    int tid = threadIdx.x;
    float L = 0.f, A = 0.f;
    for (int i = tid; i < 6144; i += 256) { L += g_part[i*2]; A += g_part[i*2+1]; }
    sl[tid] = L; sa[tid] = A;
    __syncthreads();
    for (int o = 128; o; o >>= 1) {
        if (tid < o) { sl[tid] += sl[tid+o]; sa[tid] += sa[tid+o]; }
        __syncthreads();
    }
    if (tid == 0) {
        out[0] = sl[0] / (float)NROWS_L;
        out[1] = sa[0] / (float)NROWS_L * 100.f;
    }
}

// ---------------- copy z and c into d_out (8B-aligned dst) ---------------
__global__ void copyout_kernel(float* __restrict__ out)
{
    long i = (long)blockIdx.x * 256 + threadIdx.x;
    float2* dst = (float2*)(out + 2);
    const long NZ2 = 2097152;
    const long NC2 = 4194304;
    if (i < NZ2) {
        dst[i] = ((const float2*)g_z)[i];
    } else if (i < NZ2 + NC2) {
        dst[i] = ((const float2*)g_c)[i - NZ2];
    }
}

// ---------------- host launcher ------------------------------------------
extern "C" void kernel_launch(void* const* d_in, const int* in_sizes, int n_in,
                              void* d_out, int out_size)
{
    const float* rr  = (const float*)d_in[0];
    const float* w1  = (const float*)d_in[1];
    const float* b1  = (const float*)d_in[2];
    const float* w2  = (const float*)d_in[3];
    const float* b2  = (const float*)d_in[4];
    const float* Wih = (const float*)d_in[5];
    const float* Whh = (const float*)d_in[6];
    const float* bih = (const float*)d_in[7];
    const float* bhh = (const float*)d_in[8];
    const float* Wkw = (const float*)d_in[9];
    const float* Wkb = (const float*)d_in[10];

    float* out = (float*)d_out;

    float *pz, *pc, *ph1, *pgx, *pU, *pw1T, *pw2T, *pWkT;
    cudaGetSymbolAddress((void**)&pz,   g_z);
    cudaGetSymbolAddress((void**)&pc,   g_c);
    cudaGetSymbolAddress((void**)&ph1,  g_h1);
    cudaGetSymbolAddress((void**)&pgx,  g_gx);
    cudaGetSymbolAddress((void**)&pU,   g_U);
    cudaGetSymbolAddress((void**)&pw1T, g_w1T);
    cudaGetSymbolAddress((void**)&pw2T, g_w2T);
    cudaGetSymbolAddress((void**)&pWkT, g_WkT);

    cudaFuncSetAttribute(logits_mma, cudaFuncAttributeMaxDynamicSharedMemorySize, LOG_SMEM);
    cudaFuncSetAttribute(gru6,       cudaFuncAttributeMaxDynamicSharedMemorySize, GRU6_SMEM);
    cudaFuncSetAttribute(mma_gemm,   cudaFuncAttributeMaxDynamicSharedMemorySize, GEMM_SMEM);

    // 0-1. weight transposes
    prep_a<<<256, 256>>>(w1, w2);
    prep_b<<<1536, 256>>>(Wkw);
    // 2. encoder layer 1 (relu)
    mma_gemm<<<dim3(2, 256, 1), 256, GEMM_SMEM>>>(
        rr, pw1T, b1, ph1, N_BT, 256, 256, 1, 0, 0, 0, 0);
    // 3. encoder layer 2 -> normalized z (mode 2)
    mma_gemm<<<dim3(1, 256, 1), 256, GEMM_SMEM>>>(
        ph1, pw2T, b2, pz, N_BT, 128, 256, 0, 2, 0, 0, 0);
    // 4. gx = z @ W_ih^T + b_ih
    mma_gemm<<<dim3(6, 256, 1), 256, GEMM_SMEM>>>(
        pz, Wih, bih, pgx, N_BT, 768, 128, 0, 0, 0, 0, 0);
    // 5. GRU v6
    gru6<<<128, 256, GRU6_SMEM>>>(Whh, bhh);
    // 6. U[k] = rowscale10(c @ Wk_w[k] + Wk_b[k])  (mode 1)
    mma_gemm<<<dim3(1, 256, 12), 256, GEMM_SMEM>>>(
        pc, pWkT, Wkb, pU, N_BT, 128, 256, 0, 1,
        32768L, 128L, (long)N_BT * 128);
    // 7. fused logits + reductions
    logits_mma<<<dim3(4, 128, 12), 256, LOG_SMEM>>>();
    // 8. final loss/accuracy
    final_kernel<<<1, 256>>>(out);
    // 9. copy z_seq and c_seq into d_out
    copyout_kernel<<<24576, 256>>>(out);
}

// round 15
// speedup vs baseline: 1.1316x; 1.0302x over previous
#include <cuda_runtime.h>
#include <math.h>
#include <stdint.h>

// B=128, T=256, W=256, D=128, C=256, K=12, Tp=244, TEMP=0.1
#define N_BT     32768
#define TP       244
#define NROWS_L  374784
#define GEMM_SMEM ((4*4608 + 128)*4)
#define LOG_SMEM  ((4608 + 18432 + 832)*4)
#define GRU6_SMEM (2*2048*4)

// ---------------- packed f32x2 helpers -----------------------------------
#define FMA2(d,a,b) asm("fma.rn.f32x2 %0, %1, %2, %0;" : "+l"(d) : "l"(a), "l"(b))
__device__ __forceinline__ void unpack2(unsigned long long v, float& lo, float& hi) {
    asm("mov.b64 {%0, %1}, %2;" : "=f"(lo), "=f"(hi) : "l"(v));
}
__device__ __forceinline__ float pairsum(unsigned long long v) {
    float a, b; unpack2(v, a, b); return a + b;
}
__device__ __forceinline__ uint32_t s2u(const void* p) {
    uint32_t a; asm("{ .reg .u64 t; cvta.to.shared.u64 t, %1; cvt.u32.u64 %0, t; }" : "=r"(a) : "l"(p));
    return a;
}
__device__ __forceinline__ uint32_t mapa_u32(uint32_t addr, uint32_t rank) {
    uint32_t r; asm("mapa.shared::cluster.u32 %0, %1, %2;" : "=r"(r) : "r"(addr), "r"(rank));
    return r;
}
__device__ __forceinline__ void st_cluster_f32(uint32_t addr, float v) {
    asm volatile("st.shared::cluster.f32 [%0], %1;" :: "r"(addr), "f"(v) : "memory");
}
__device__ __forceinline__ float fsig(float x)  { return 1.f / (1.f + __expf(-x)); }
__device__ __forceinline__ float ftanh(float x) { return 1.f - 2.f / (1.f + __expf(2.f*x)); }

// ---------------- tf32 mma helpers ---------------------------------------
__device__ __forceinline__ uint32_t f2tf(float x) {
    uint32_t r; asm("cvt.rna.tf32.f32 %0, %1;" : "=r"(r) : "f"(x)); return r;
}
__device__ __forceinline__ void cvt_hl(float4 x, uint4& h, uint4& l) {
    h.x = f2tf(x.x); l.x = f2tf(x.x - __uint_as_float(h.x));
    h.y = f2tf(x.y); l.y = f2tf(x.y - __uint_as_float(h.y));
    h.z = f2tf(x.z); l.z = f2tf(x.z - __uint_as_float(h.z));
    h.w = f2tf(x.w); l.w = f2tf(x.w - __uint_as_float(h.w));
}
__device__ __forceinline__ void cvt_h(float4 x, uint4& h) {
    h.x = f2tf(x.x); h.y = f2tf(x.y); h.z = f2tf(x.z); h.w = f2tf(x.w);
}
__device__ __forceinline__ void mma8(float* c, const uint32_t* a, const uint32_t* b) {
    asm volatile("mma.sync.aligned.m16n8k8.row.col.f32.tf32.tf32.f32 "
        "{%0,%1,%2,%3}, {%4,%5,%6,%7}, {%8,%9}, {%0,%1,%2,%3};"
        : "+f"(c[0]), "+f"(c[1]), "+f"(c[2]), "+f"(c[3])
        : "r"(a[0]), "r"(a[1]), "r"(a[2]), "r"(a[3]), "r"(b[0]), "r"(b[1]));
}

// ---------------- scratch ------------------------------------------------
__device__ __align__(16) float g_z   [4194304];
__device__ __align__(16) float g_c   [8388608];
__device__ __align__(16) float g_h1  [8388608];
__device__ __align__(16) float g_gx  [25165824];
__device__ __align__(16) float g_U   [50331648];
__device__ __align__(16) float g_w1T [65536];
__device__ __align__(16) float g_w2T [32768];
__device__ __align__(16) float g_WkT [393216];
__device__ __align__(16) float g_part[12288];

// ---------------- prep: transposes ---------------------------------------
__global__ void prep_a(const float* __restrict__ w1, const float* __restrict__ w2)
{
    long i = (long)blockIdx.x * 256 + threadIdx.x;
    if (i < 65536) {
        int n = (int)(i >> 8), k = (int)(i & 255);
        g_w1T[n*256 + k] = w1[k*256 + n];
    }
    if (i < 32768) {
        int n = (int)(i >> 8), k = (int)(i & 255);
        g_w2T[n*256 + k] = w2[k*128 + n];
    }
}
__global__ void prep_b(const float* __restrict__ wk)
{
    long i = (long)blockIdx.x * 256 + threadIdx.x;
    if (i < 393216) {
        long kk = i / 32768; long r = i % 32768;
        int d = (int)(r >> 8), c = (int)(r & 255);
        g_WkT[kk*32768 + d*256 + c] = wk[kk*32768 + c*128 + d];
    }
}

// ---------------- TF32 mma.sync NT-GEMM (single-buffer, 2 CTAs/SM) -------
// C = A @ B^T + bias. full3: 1 = 3-term compensation (+al*bh), 0 = 2-term.
// mode 0: plain(+relu); 1: rows *= 10/max(||r||,eps); 2: rows *= 1/..; need N==128.
__global__ __launch_bounds__(256, 2) void mma_gemm(
    const float* __restrict__ A, const float* __restrict__ Bm,
    const float* __restrict__ bias, float* __restrict__ Cm,
    int M, int N, int K, int relu, int mode, int full3,
    long sB, long sBias, long sC)
{
    extern __shared__ uint32_t smu[];
    uint32_t* Ah = smu;
    uint32_t* Al = smu + 4608;
    uint32_t* Bh = smu + 9216;
    uint32_t* Bl = smu + 13824;
    float* sbias = (float*)(smu + 18432);
    float* rs    = (float*)smu;
    float* rinv  = (float*)(smu + 2176);

    const float* Bz = Bm  + (long)blockIdx.z * sB;
    const float* bz = bias + (long)blockIdx.z * sBias;
    float*       Cz = Cm  + (long)blockIdx.z * sC;
    int m0 = blockIdx.y * 128, n0 = blockIdx.x * 128;

    int tid = threadIdx.x;
    int wid = tid >> 5, lane = tid & 31;
    int wm = wid >> 2, wn = wid & 3;
    int gid = lane >> 2, tig = lane & 3;

    if (tid < 128) sbias[tid] = bz[n0 + tid];

    const float* Ag = A  + (long)m0 * K;
    const float* Bg = Bz + (long)n0 * K;

    float c[4][4][4];
    #pragma unroll
    for (int i = 0; i < 4; i++)
        #pragma unroll
        for (int j = 0; j < 4; j++)
            #pragma unroll
            for (int q = 0; q < 4; q++) c[i][j][q] = 0.f;

    int NC = K >> 5;
    for (int kc = 0; kc < NC; kc++) {
        int k0 = kc * 32;
        __syncthreads();
        #pragma unroll
        for (int l = 0; l < 4; l++) {
            int u = tid + l*256, r = u >> 3, c4 = u & 7;
            float4 va = *(const float4*)(Ag + (long)r*K + k0 + c4*4);
            float4 vb = *(const float4*)(Bg + (long)r*K + k0 + c4*4);
            uint4 h, lo;
            if (full3) {
                cvt_hl(va, h, lo);
                *(uint4*)(Ah + r*36 + c4*4) = h;
                *(uint4*)(Al + r*36 + c4*4) = lo;
            } else {
                cvt_h(va, h);
                *(uint4*)(Ah + r*36 + c4*4) = h;
            }
            cvt_hl(vb, h, lo);
            *(uint4*)(Bh + r*36 + c4*4) = h;
            *(uint4*)(Bl + r*36 + c4*4) = lo;
        }
        __syncthreads();
        #pragma unroll
        for (int ks = 0; ks < 4; ks++) {
            int k = ks * 8;
            uint32_t ah[4][4], al[4][4];
            #pragma unroll
            for (int i = 0; i < 4; i++) {
                int r0 = wm*64 + i*16 + gid;
                ah[i][0] = Ah[r0*36 + k + tig];
                ah[i][1] = Ah[(r0+8)*36 + k + tig];
                ah[i][2] = Ah[r0*36 + k + tig + 4];
                ah[i][3] = Ah[(r0+8)*36 + k + tig + 4];
                if (full3) {
                    al[i][0] = Al[r0*36 + k + tig];
                    al[i][1] = Al[(r0+8)*36 + k + tig];
                    al[i][2] = Al[r0*36 + k + tig + 4];
                    al[i][3] = Al[(r0+8)*36 + k + tig + 4];
                }
            }
            #pragma unroll
            for (int j = 0; j < 4; j++) {
                int n = wn*32 + j*8 + gid;
                uint32_t bh[2], bl[2];
                bh[0] = Bh[n*36 + k + tig];
                bh[1] = Bh[n*36 + k + tig + 4];
                bl[0] = Bl[n*36 + k + tig];
                bl[1] = Bl[n*36 + k + tig + 4];
                #pragma unroll
                for (int i = 0; i < 4; i++) {
                    mma8(c[i][j], ah[i], bh);
                    mma8(c[i][j], ah[i], bl);
                    if (full3) mma8(c[i][j], al[i], bh);
                }
            }
        }
    }

    #pragma unroll
    for (int i = 0; i < 4; i++)
        #pragma unroll
        for (int j = 0; j < 4; j++) {
            int colb = wn*32 + j*8 + tig*2;
            c[i][j][0] += sbias[colb]; c[i][j][1] += sbias[colb+1];
            c[i][j][2] += sbias[colb]; c[i][j][3] += sbias[colb+1];
        }

    if (mode == 0) {
        #pragma unroll
        for (int i = 0; i < 4; i++) {
            int r0 = m0 + wm*64 + i*16 + gid;
            #pragma unroll
            for (int j = 0; j < 4; j++) {
                int colb = n0 + wn*32 + j*8 + tig*2;
                float2 v0 = make_float2(c[i][j][0], c[i][j][1]);
                float2 v1 = make_float2(c[i][j][2], c[i][j][3]);
                if (relu) {
                    v0.x = fmaxf(v0.x, 0.f); v0.y = fmaxf(v0.y, 0.f);
                    v1.x = fmaxf(v1.x, 0.f); v1.y = fmaxf(v1.y, 0.f);
                }
                *(float2*)(Cz + (long)r0*N + colb)     = v0;
                *(float2*)(Cz + (long)(r0+8)*N + colb) = v1;
            }
        }
    } else {
        __syncthreads();
        #pragma unroll
        for (int i = 0; i < 4; i++) {
            float ss0 = 0.f, ss1 = 0.f;
            #pragma unroll
            for (int j = 0; j < 4; j++) {
                ss0 += c[i][j][0]*c[i][j][0] + c[i][j][1]*c[i][j][1];
                ss1 += c[i][j][2]*c[i][j][2] + c[i][j][3]*c[i][j][3];
            }
            int r0 = wm*64 + i*16 + gid;
            rs[r0*17 + wn*4 + tig]     = ss0;
            rs[(r0+8)*17 + wn*4 + tig] = ss1;
        }
        __syncthreads();
        if (tid < 128) {
            float ss = 0.f;
            #pragma unroll
            for (int x = 0; x < 16; x++) ss += rs[tid*17 + x];
            float inv = 1.f / fmaxf(sqrtf(ss), 1e-12f);
            if (mode == 1) inv *= 10.f;
            rinv[tid] = inv;
        }
        __syncthreads();
        #pragma unroll
        for (int i = 0; i < 4; i++) {
            int rr = wm*64 + i*16 + gid;
            float sc0 = rinv[rr], sc1 = rinv[rr+8];
            int r0 = m0 + rr;
            #pragma unroll
            for (int j = 0; j < 4; j++) {
                int colb = n0 + wn*32 + j*8 + tig*2;
                *(float2*)(Cz + (long)r0*N + colb) =
                    make_float2(c[i][j][0]*sc0, c[i][j][1]*sc0);
                *(float2*)(Cz + (long)(r0+8)*N + colb) =
                    make_float2(c[i][j][2]*sc1, c[i][j][3]*sc1);
            }
        }
    }
}

// ---------------- logits via 2-term TF32 mma (single-buffer, 2 CTAs/SM) --
// grid (4 t-tiles, 128 b, 12 k); block 256. Tile 64(t) x 256(s) x 128(d).
// U side: hi only (2-term); Z side keeps hi+lo.
__global__ __launch_bounds__(256, 2) void logits_mma()
{
    extern __shared__ uint32_t smu[];
    uint32_t* Uh = smu;                 // 2304 (Ul slot unused)
    uint32_t* Zh = smu + 4608;
    uint32_t* Zl = smu + 13824;
    float* redL = (float*)(smu + 23040);
    float* redM = redL + 256;
    float* redP = redM + 256;
    float* wred = redP + 256;

    int tile = blockIdx.x, b = blockIdx.y, kk = blockIdx.z;
    int t0 = tile * 64;
    int tid = threadIdx.x;
    int wid = tid >> 5, lane = tid & 31;
    int wm = wid >> 2, wn = wid & 3;
    int gid = lane >> 2, tig = lane & 3;

    const float* Ug = g_U + ((long)kk*32768 + (long)b*256 + t0) * 128;
    const float* Zg = g_z + (long)b * 32768;

    float c[2][8][4];
    #pragma unroll
    for (int i = 0; i < 2; i++)
        #pragma unroll
        for (int j = 0; j < 8; j++)
            #pragma unroll
            for (int q = 0; q < 4; q++) c[i][j][q] = 0.f;

    #pragma unroll
    for (int kc = 0; kc < 4; kc++) {
        int k0 = kc * 32;
        __syncthreads();
        #pragma unroll
        for (int l = 0; l < 8; l++) {
            int u = tid + l*256, r = u >> 3, c4 = u & 7;
            float4 v = *(const float4*)(Zg + (long)r*128 + k0 + c4*4);
            uint4 h, lo; cvt_hl(v, h, lo);
            *(uint4*)(Zh + r*36 + c4*4) = h;
            *(uint4*)(Zl + r*36 + c4*4) = lo;
        }
        #pragma unroll
        for (int l = 0; l < 2; l++) {
            int u = tid + l*256, r = u >> 3, c4 = u & 7;
            float4 v = *(const float4*)(Ug + (long)r*128 + k0 + c4*4);
            uint4 h; cvt_h(v, h);
            *(uint4*)(Uh + r*36 + c4*4) = h;
        }
        __syncthreads();
        #pragma unroll
        for (int ks = 0; ks < 4; ks++) {
            int k = ks * 8;
            uint32_t ah[2][4];
            #pragma unroll
            for (int i = 0; i < 2; i++) {
                int r0 = wm*32 + i*16 + gid;
                ah[i][0] = Uh[r0*36 + k + tig];
                ah[i][1] = Uh[(r0+8)*36 + k + tig];
                ah[i][2] = Uh[r0*36 + k + tig + 4];
                ah[i][3] = Uh[(r0+8)*36 + k + tig + 4];
            }
            #pragma unroll
            for (int j = 0; j < 8; j++) {
                int n = wn*64 + j*8 + gid;
                uint32_t bh[2], bl[2];
                bh[0] = Zh[n*36 + k + tig];
                bh[1] = Zh[n*36 + k + tig + 4];
                bl[0] = Zl[n*36 + k + tig];
                bl[1] = Zl[n*36 + k + tig + 4];
                #pragma unroll
                for (int i = 0; i < 2; i++) {
                    mma8(c[i][j], ah[i], bh);
                    mma8(c[i][j], ah[i], bl);
                }
            }
        }
    }

    #pragma unroll
    for (int i = 0; i < 2; i++) {
        #pragma unroll
        for (int sub = 0; sub < 2; sub++) {
            int rrow = wm*32 + i*16 + sub*8 + gid;
            int spos = t0 + rrow + kk + 1;
            float lsum = 0.f, nmax = -3.0e38f, pos = -3.0e38f;
            #pragma unroll
            for (int j = 0; j < 8; j++) {
                #pragma unroll
                for (int p = 0; p < 2; p++) {
                    int col = wn*64 + j*8 + tig*2 + p;
                    float l = c[i][j][sub*2 + p];
                    lsum += __expf(l);
                    if (col == spos) pos = l;
                    else             nmax = fmaxf(nmax, l);
                }
            }
            #pragma unroll
            for (int o = 1; o <= 2; o <<= 1) {
                lsum += __shfl_xor_sync(0xffffffffu, lsum, o);
                nmax = fmaxf(nmax, __shfl_xor_sync(0xffffffffu, nmax, o));
                pos  = fmaxf(pos,  __shfl_xor_sync(0xffffffffu, pos,  o));
            }
            if (tig == 0) {
                redL[wn*64 + rrow] = lsum;
                redM[wn*64 + rrow] = nmax;
                redP[wn*64 + rrow] = pos;
            }
        }
    }
    __syncthreads();

    float loss_tot = 0.f, acc_tot = 0.f;
    if (tid < 64) {
        float ls = redL[tid] + redL[64+tid] + redL[128+tid] + redL[192+tid];
        float nm = fmaxf(fmaxf(redM[tid], redM[64+tid]), fmaxf(redM[128+tid], redM[192+tid]));
        float ps = fmaxf(fmaxf(redP[tid], redP[64+tid]), fmaxf(redP[128+tid], redP[192+tid]));
        int t = t0 + tid;
        if (t < TP) {
            loss_tot = logf(ls) - ps;
            acc_tot  = (ps >= nm) ? 1.f : 0.f;
        }
    }
    if (wid < 2) {
        #pragma unroll
        for (int o = 16; o; o >>= 1) {
            loss_tot += __shfl_xor_sync(0xffffffffu, loss_tot, o);
            acc_tot  += __shfl_xor_sync(0xffffffffu, acc_tot,  o);
        }
        if (lane == 0) { wred[wid*2] = loss_tot; wred[wid*2+1] = acc_tot; }
    }
    __syncthreads();
    if (tid == 0) {
        long bid = ((long)kk*128 + b)*4 + tile;
        g_part[bid*2]   = wred[0] + wred[2];
        g_part[bid*2+1] = wred[1] + wred[3];
    }
}

// ---------------- GRU v6 (unchanged) --------------------------------------
__global__ __launch_bounds__(256, 1) __cluster_dims__(8, 1, 1)
void gru6(const float* __restrict__ Whh, const float* __restrict__ bhh)
{
    extern __shared__ float s[];
    float* hb = s;                         // [2][2048]

    int tid  = threadIdx.x;
    int rank = blockIdx.x & 7;
    int cl   = blockIdx.x >> 3;
    int co   = rank * 32;
    int b0   = cl * 8;
    int c    = tid >> 3, ks = tid & 7;

    unsigned long long w0r[16], w1r[16], w2r[16];
    {
        const float* p0 = Whh + ((long)(0*256 + co + c))*256 + ks*32;
        const float* p1 = Whh + ((long)(1*256 + co + c))*256 + ks*32;
        const float* p2 = Whh + ((long)(2*256 + co + c))*256 + ks*32;
        #pragma unroll
        for (int i = 0; i < 16; i++) {
            w0r[i] = *(const unsigned long long*)(p0 + i*2);
            w1r[i] = *(const unsigned long long*)(p1 + i*2);
            w2r[i] = *(const unsigned long long*)(p2 + i*2);
        }
    }
    float bhr0 = bhh[co + c], bhr1 = bhh[256 + co + c], bhr2 = bhh[512 + co + c];

    for (int i = tid; i < 2*2048; i += 256) hb[i] = 0.f;

    const float* gxp = g_gx + ((long)(b0 + ks) * 256) * 768 + co + c;
    float*       cp  = g_c  + ((long)(b0 + ks) * 256) * 256 + co + c;
    int kg = co + c;
    int slot = ((ks*8 + ((kg >> 2) & 7))*8 + (kg >> 5))*4 + (kg & 3);
    uint32_t ladr = s2u(hb) + (uint32_t)(slot * 4);
    uint32_t radr[8];
    #pragma unroll
    for (int r = 0; r < 8; r++) radr[r] = mapa_u32(ladr, r);

    float h_old = 0.f;
    float xr = gxp[0], xz = gxp[256], xn = gxp[512];

    __syncthreads();
    asm volatile("barrier.cluster.arrive.aligned;" ::: "memory");
    asm volatile("barrier.cluster.wait.aligned;"   ::: "memory");

    for (int t = 0; t < 256; t++) {
        int p = t & 1, pn = p ^ 1;
        float xr_n = 0.f, xz_n = 0.f, xn_n = 0.f;
        if (t < 255) {
            const float* gq = gxp + (long)(t + 1) * 768;
            xr_n = gq[0]; xz_n = gq[256]; xn_n = gq[512];
        }

        const float* hp = hb + p*2048 + ks*4;
        float sg0[8], sg1[8], sg2[8];
        #pragma unroll
        for (int b = 0; b < 8; b++) {
            const float* hq = hp + b*256;
            unsigned long long a0 = 0ULL, a1 = 0ULL, a2 = 0ULL;
            #pragma unroll
            for (int j4 = 0; j4 < 8; j4++) {
                ulonglong2 h4 = *(const ulonglong2*)(hq + j4*32);
                FMA2(a0, w0r[j4*2], h4.x); FMA2(a0, w0r[j4*2+1], h4.y);
                FMA2(a1, w1r[j4*2], h4.x); FMA2(a1, w1r[j4*2+1], h4.y);
                FMA2(a2, w2r[j4*2], h4.x); FMA2(a2, w2r[j4*2+1], h4.y);
            }
            sg0[b] = pairsum(a0); sg1[b] = pairsum(a1); sg2[b] = pairsum(a2);
        }

        float t0g[4], t1g[4], t2g[4];
        bool hi4 = (ks & 4) != 0;
        #pragma unroll
        for (int i = 0; i < 4; i++) {
            float s0 = hi4 ? sg0[i] : sg0[i+4];
            float k0 = hi4 ? sg0[i+4] : sg0[i];
            t0g[i] = k0 + __shfl_xor_sync(0xffffffffu, s0, 4);
            float s1 = hi4 ? sg1[i] : sg1[i+4];
            float k1 = hi4 ? sg1[i+4] : sg1[i];
            t1g[i] = k1 + __shfl_xor_sync(0xffffffffu, s1, 4);
            float s2 = hi4 ? sg2[i] : sg2[i+4];
            float k2 = hi4 ? sg2[i+4] : sg2[i];
            t2g[i] = k2 + __shfl_xor_sync(0xffffffffu, s2, 4);
        }
        float u0g[2], u1g[2], u2g[2];
        bool hi2 = (ks & 2) != 0;
        #pragma unroll
        for (int i = 0; i < 2; i++) {
            float s0 = hi2 ? t0g[i] : t0g[i+2];
            float k0 = hi2 ? t0g[i+2] : t0g[i];
            u0g[i] = k0 + __shfl_xor_sync(0xffffffffu, s0, 2);
            float s1 = hi2 ? t1g[i] : t1g[i+2];
            float k1 = hi2 ? t1g[i+2] : t1g[i];
            u1g[i] = k1 + __shfl_xor_sync(0xffffffffu, s1, 2);
            float s2 = hi2 ? t2g[i] : t2g[i+2];
            float k2 = hi2 ? t2g[i+2] : t2g[i];
            u2g[i] = k2 + __shfl_xor_sync(0xffffffffu, s2, 2);
        }
        bool hi1 = (ks & 1) != 0;
        float s0 = hi1 ? u0g[0] : u0g[1];
        float k0 = hi1 ? u0g[1] : u0g[0];
        float hr = k0 + __shfl_xor_sync(0xffffffffu, s0, 1) + bhr0;
        float s1 = hi1 ? u1g[0] : u1g[1];
        float k1 = hi1 ? u1g[1] : u1g[0];
        float hz = k1 + __shfl_xor_sync(0xffffffffu, s1, 1) + bhr1;
        float s2 = hi1 ? u2g[0] : u2g[1];
        float k2 = hi1 ? u2g[1] : u2g[0];
        float hn = k2 + __shfl_xor_sync(0xffffffffu, s2, 1) + bhr2;

        float rg = fsig(xr + hr);
        float zg = fsig(xz + hz);
        float ng = ftanh(xn + rg*hn);
        float hnew = (1.f - zg)*ng + zg*h_old;
        h_old = hnew;

        uint32_t off = (uint32_t)(pn * 8192);
        #pragma unroll
        for (int r = 0; r < 8; r++) st_cluster_f32(radr[r] + off, hnew);
        cp[(long)t*256] = hnew;

        xr = xr_n; xz = xz_n; xn = xn_n;

        asm volatile("barrier.cluster.arrive.aligned;" ::: "memory");
        asm volatile("barrier.cluster.wait.aligned;"   ::: "memory");
    }
}

// ---------------- final reduction ---------------------------------------
__global__ void final_kernel(float* __restrict__ out)
{
    __shared__ float sl[256], sa[256];
    int tid = threadIdx.x;
    float L = 0.f, A = 0.f;
    for (int i = tid; i < 6144; i += 256) { L += g_part[i*2]; A += g_part[i*2+1]; }
    sl[tid] = L; sa[tid] = A;
    __syncthreads();
    for (int o = 128; o; o >>= 1) {
        if (tid < o) { sl[tid] += sl[tid+o]; sa[tid] += sa[tid+o]; }
        __syncthreads();
    }
    if (tid == 0) {
        out[0] = sl[0] / (float)NROWS_L;
        out[1] = sa[0] / (float)NROWS_L * 100.f;
    }
}

// ---------------- copy z and c into d_out (8B-aligned dst) ---------------
__global__ void copyout_kernel(float* __restrict__ out)
{
    long i = (long)blockIdx.x * 256 + threadIdx.x;
    float2* dst = (float2*)(out + 2);
    const long NZ2 = 2097152;
    const long NC2 = 4194304;
    if (i < NZ2) {
        dst[i] = ((const float2*)g_z)[i];
    } else if (i < NZ2 + NC2) {
        dst[i] = ((const float2*)g_c)[i - NZ2];
    }
}

// ---------------- host launcher ------------------------------------------
extern "C" void kernel_launch(void* const* d_in, const int* in_sizes, int n_in,
                              void* d_out, int out_size)
{
    const float* rr  = (const float*)d_in[0];
    const float* w1  = (const float*)d_in[1];
    const float* b1  = (const float*)d_in[2];
    const float* w2  = (const float*)d_in[3];
    const float* b2  = (const float*)d_in[4];
    const float* Wih = (const float*)d_in[5];
    const float* Whh = (const float*)d_in[6];
    const float* bih = (const float*)d_in[7];
    const float* bhh = (const float*)d_in[8];
    const float* Wkw = (const float*)d_in[9];
    const float* Wkb = (const float*)d_in[10];

    float* out = (float*)d_out;

    float *pz, *pc, *ph1, *pgx, *pU, *pw1T, *pw2T, *pWkT;
    cudaGetSymbolAddress((void**)&pz,   g_z);
    cudaGetSymbolAddress((void**)&pc,   g_c);
    cudaGetSymbolAddress((void**)&ph1,  g_h1);
    cudaGetSymbolAddress((void**)&pgx,  g_gx);
    cudaGetSymbolAddress((void**)&pU,   g_U);
    cudaGetSymbolAddress((void**)&pw1T, g_w1T);
    cudaGetSymbolAddress((void**)&pw2T, g_w2T);
    cudaGetSymbolAddress((void**)&pWkT, g_WkT);

    cudaFuncSetAttribute(logits_mma, cudaFuncAttributeMaxDynamicSharedMemorySize, LOG_SMEM);
    cudaFuncSetAttribute(gru6,       cudaFuncAttributeMaxDynamicSharedMemorySize, GRU6_SMEM);
    cudaFuncSetAttribute(mma_gemm,   cudaFuncAttributeMaxDynamicSharedMemorySize, GEMM_SMEM);

    // 0-1. weight transposes
    prep_a<<<256, 256>>>(w1, w2);
    prep_b<<<1536, 256>>>(Wkw);
    // 2. encoder layer 1 (relu, 3-term)
    mma_gemm<<<dim3(2, 256, 1), 256, GEMM_SMEM>>>(
        rr, pw1T, b1, ph1, N_BT, 256, 256, 1, 0, 1, 0, 0, 0);
    // 3. encoder layer 2 -> normalized z (mode 2, 3-term)
    mma_gemm<<<dim3(1, 256, 1), 256, GEMM_SMEM>>>(
        ph1, pw2T, b2, pz, N_BT, 128, 256, 0, 2, 1, 0, 0, 0);
    // 4. gx = z @ W_ih^T + b_ih (3-term)
    mma_gemm<<<dim3(6, 256, 1), 256, GEMM_SMEM>>>(
        pz, Wih, bih, pgx, N_BT, 768, 128, 0, 0, 1, 0, 0, 0);
    // 5. GRU v6
    gru6<<<128, 256, GRU6_SMEM>>>(Whh, bhh);
    // 6. U[k] = rowscale10(c @ Wk_w[k] + Wk_b[k])  (mode 1, 2-term)
    mma_gemm<<<dim3(1, 256, 12), 256, GEMM_SMEM>>>(
        pc, pWkT, Wkb, pU, N_BT, 128, 256, 0, 1, 0,
        32768L, 128L, (long)N_BT * 128);
    // 7. fused logits + reductions (2-term)
    logits_mma<<<dim3(4, 128, 12), 256, LOG_SMEM>>>();
    // 8. final loss/accuracy
    final_kernel<<<1, 256>>>(out);
    // 9. copy z_seq and c_seq into d_out
    copyout_kernel<<<24576, 256>>>(out);
}